// round 9
// baseline (speedup 1.0000x reference)
#include <cuda_runtime.h>
#include <cuda_bf16.h>
#include <math.h>

// ---------------------------------------------------------------------------
// RTE forward (word-by-word attention entailment model), fp32.
// B=128, T=128, NDIM=512, EMB=300, G=3*NDIM=1536, VOCAB=50000.
//
// R8 (= complete R7): fma.rn.f32x2 everywhere; re-tiled persistent loops with
// duplicated-weight smem; K=1024 concat GEMM in match step; flag-array grid
// barrier. 7 launches.
// ---------------------------------------------------------------------------

#define B_   128
#define T_   128
#define N_   512
#define E_   300
#define G_   1536
#define TBN_ (T_ * B_)   // 16384
#define NBLK 128

typedef unsigned long long u64;

// ------------------------------- scratch (static device memory) ------------
__device__ float g_GiP[TBN_ * G_];
__device__ float g_GiH[TBN_ * G_];
__device__ float g_oP [TBN_ * N_];
__device__ float g_oH [TBN_ * N_];
__device__ float g_Yw [TBN_ * N_];
__device__ float g_hWh[TBN_ * N_];
__device__ float g_gihp[TBN_ * G_];
__device__ float g_h0[B_ * N_];
__device__ float g_h1[B_ * N_];
__device__ float g_r0[B_ * N_];
__device__ float g_r1[B_ * N_];
__device__ float g_s  [B_ * N_];
__device__ float g_a  [B_ * N_];
__device__ float g_maskP[T_ * B_];
__device__ float g_maskH[T_ * B_];
__device__ float g_WyT[N_ * N_];
__device__ float g_WhT[N_ * N_];
__device__ float g_WrT[N_ * N_];
__device__ float g_WpP[G_ * N_];
__device__ float g_bpP[G_];
__device__ float g_WpH[G_ * N_];
__device__ float g_bpH[G_];
__device__ float g_WpM[G_ * N_];
__device__ float g_bpM[G_];
__device__ float g_AihP[G_ * N_];
__device__ float g_mWihH[G_ * N_];
__device__ volatile unsigned g_flagsA[NBLK];
__device__ volatile unsigned g_flagsB[NBLK];

extern __shared__ __align__(16) char g_dynsm[];

// ------------------------------- f32x2 helpers ------------------------------
__device__ __forceinline__ u64 pk2(float lo, float hi) {
    u64 r; asm("mov.b64 %0, {%1, %2};" : "=l"(r) : "f"(lo), "f"(hi)); return r;
}
__device__ __forceinline__ u64 dup2(float v) { return pk2(v, v); }
__device__ __forceinline__ void fma2(u64& d, u64 a, u64 b) {
    asm("fma.rn.f32x2 %0, %1, %2, %0;" : "+l"(d) : "l"(a), "l"(b));
}
__device__ __forceinline__ float2 up2(u64 v) {
    float2 f; asm("mov.b64 {%0, %1}, %2;" : "=f"(f.x), "=f"(f.y) : "l"(v));
    return f;
}

// ------------------------------- math helpers ------------------------------
__device__ __forceinline__ float sigm_f(float x) {
    return 1.0f / (1.0f + __expf(-x));
}
__device__ __forceinline__ float tanh_f(float x) {
    float e = __expf(-2.0f * fabsf(x));
    float t = (1.0f - e) / (1.0f + e);
    return copysignf(t, x);
}
__device__ __forceinline__ float tanh_fast(float x) {
    float y;
    asm("tanh.approx.f32 %0, %1;" : "=f"(y) : "f"(x));
    return y;
}

// ------------------------------- grid barrier (flag array) ------------------
__device__ __forceinline__ void grid_bar(volatile unsigned* flags,
                                         unsigned epoch) {
    __threadfence();
    __syncthreads();
    if (threadIdx.x == 0) flags[blockIdx.x] = epoch;
    if (threadIdx.x < 32) {
        for (int i = (int)threadIdx.x; i < NBLK; i += 32)
            while (flags[i] < epoch) __nanosleep(32);
    }
    __threadfence();
    __syncthreads();
}

// ------------------------------- fused prep --------------------------------
__global__ void prep_k(const int* __restrict__ prem,
                       const int* __restrict__ hyp,
                       const float* __restrict__ Wy,
                       const float* __restrict__ Wh,
                       const float* __restrict__ Wr,
                       const float* __restrict__ pWhh,
                       const float* __restrict__ pbhh,
                       const float* __restrict__ hWhh,
                       const float* __restrict__ hbhh,
                       const float* __restrict__ mWhh,
                       const float* __restrict__ mbhh,
                       const float* __restrict__ mWih) {
    long i = (long)blockIdx.x * 256 + threadIdx.x;
    if (i < 16384) {
        int t = (int)i >> 7, b = (int)i & 127;
        g_maskP[i] = (prem[b * T_ + t] != 0) ? 1.0f : 0.0f;
        g_maskH[i] = (hyp [b * T_ + t] != 0) ? 1.0f : 0.0f;
        if (i < NBLK) { g_flagsA[i] = 0u; g_flagsB[i] = 0u; }
        return;
    }
    i -= 16384;
    if (i < 65536) { g_h0[i] = 0.0f; g_r0[i] = 0.0f; return; }
    i -= 65536;
    if (i < 3 * 262144) {
        int which = (int)(i >> 18);
        int e = (int)(i & 262143);
        int r = e >> 9, c = e & 511;
        const float* src = which == 0 ? Wy : (which == 1 ? Wh : Wr);
        float* dst = which == 0 ? g_WyT : (which == 1 ? g_WhT : g_WrT);
        dst[c * N_ + r] = src[e];
        return;
    }
    i -= 3 * 262144;
    if (i < 3 * 786432) {
        int which = (int)(i / 786432);
        int e = (int)(i - (long)which * 786432);
        int j = e >> 9, k = e & 511;
        int n = j / 3, g = j - n * 3;
        const float* W = which == 0 ? pWhh : (which == 1 ? hWhh : mWhh);
        const float* b = which == 0 ? pbhh : (which == 1 ? hbhh : mbhh);
        float* Wp = which == 0 ? g_WpP : (which == 1 ? g_WpH : g_WpM);
        float* bp = which == 0 ? g_bpP : (which == 1 ? g_bpH : g_bpM);
        Wp[e] = W[(size_t)(g * N_ + n) * N_ + k];
        if (k == 0) bp[j] = b[g * N_ + n];
        return;
    }
    i -= 3 * 786432;
    if (i < 786432) {
        int j = (int)i >> 9, k = (int)i & 511;
        int n = j / 3, g = j - n * 3;
        g_AihP[i] = mWih[(size_t)(g * N_ + n) * 1024 + k];
        return;
    }
    i -= 786432;
    if (i < 786432) {
        int j = (int)i >> 9, k = (int)i & 511;
        g_mWihH[i] = mWih[(size_t)j * 1024 + 512 + k];
        return;
    }
}

// ------------------------------- big GEMM body (FFMA2) ----------------------
// C[M,N] = Aeff @ Bt^T (+bias). 128x128 tiles, TK=16, 256 thr, 8x8 micro.
__device__ __forceinline__ void gemm_body(const float* __restrict__ A,
                                          const int*   __restrict__ gidx,
                                          const float* __restrict__ Bt,
                                          const float* __restrict__ bias,
                                          float* __restrict__ C,
                                          int M, int N, int K) {
    __shared__ float As[16][132];
    __shared__ float Bs[16][132];
    int tid = threadIdx.x;
    int tx = tid & 15, ty = tid >> 4;
    int m0 = blockIdx.y * 128, n0 = blockIdx.x * 128;

    u64 acc2[8][4];
#pragma unroll
    for (int i = 0; i < 8; i++)
#pragma unroll
        for (int j = 0; j < 4; j++) acc2[i][j] = 0ull;

    int arow = m0 + (tid >> 1);
    const float* abase;
    if (gidx) {
        int tok = gidx[(arow & 127) * 128 + (arow >> 7)];
        abase = A + (size_t)tok * K;
    } else {
        abase = A + (size_t)arow * K;
    }
    int brow = n0 + (tid >> 1);
    const float* bbase = Bt + (size_t)brow * K;
    int kk = (tid & 1) * 8;
    int c = tid >> 1;

    for (int k0 = 0; k0 < K; k0 += 16) {
        float4 va0 = make_float4(0.f, 0.f, 0.f, 0.f), va1 = va0;
        float4 vb0 = va0, vb1 = va0;
        if (k0 + kk < K) {
            va0 = *(const float4*)(abase + k0 + kk);
            vb0 = *(const float4*)(bbase + k0 + kk);
        }
        if (k0 + kk + 4 < K) {
            va1 = *(const float4*)(abase + k0 + kk + 4);
            vb1 = *(const float4*)(bbase + k0 + kk + 4);
        }
        As[kk + 0][c] = va0.x; As[kk + 1][c] = va0.y;
        As[kk + 2][c] = va0.z; As[kk + 3][c] = va0.w;
        As[kk + 4][c] = va1.x; As[kk + 5][c] = va1.y;
        As[kk + 6][c] = va1.z; As[kk + 7][c] = va1.w;
        Bs[kk + 0][c] = vb0.x; Bs[kk + 1][c] = vb0.y;
        Bs[kk + 2][c] = vb0.z; Bs[kk + 3][c] = vb0.w;
        Bs[kk + 4][c] = vb1.x; Bs[kk + 5][c] = vb1.y;
        Bs[kk + 6][c] = vb1.z; Bs[kk + 7][c] = vb1.w;
        __syncthreads();
#pragma unroll
        for (int k = 0; k < 16; k++) {
            float4 a0 = *(const float4*)&As[k][ty * 8];
            float4 a1 = *(const float4*)&As[k][ty * 8 + 4];
            // B pairs read directly as u64 (register-pair reinterpretation)
            ulonglong2 bA = *(const ulonglong2*)&Bs[k][tx * 8];
            ulonglong2 bB = *(const ulonglong2*)&Bs[k][tx * 8 + 4];
            u64 bp[4] = { bA.x, bA.y, bB.x, bB.y };
            float av[8] = {a0.x, a0.y, a0.z, a0.w, a1.x, a1.y, a1.z, a1.w};
#pragma unroll
            for (int i = 0; i < 8; i++) {
                u64 ad = dup2(av[i]);
#pragma unroll
                for (int j = 0; j < 4; j++) fma2(acc2[i][j], ad, bp[j]);
            }
        }
        __syncthreads();
    }
#pragma unroll
    for (int i = 0; i < 8; i++) {
        int row = m0 + ty * 8 + i;
#pragma unroll
        for (int j = 0; j < 4; j++) {
            int col = n0 + tx * 8 + 2 * j;
            float2 v = up2(acc2[i][j]);
            if (bias) { v.x += bias[col]; v.y += bias[col + 1]; }
            C[(size_t)row * N + col]     = v.x;
            C[(size_t)row * N + col + 1] = v.y;
        }
    }
}

__global__ void __launch_bounds__(256) gemm_gi_k(
        const int* __restrict__ prem, const int* __restrict__ hyp,
        const float* __restrict__ E,
        const float* __restrict__ pWih, const float* __restrict__ pbih,
        const float* __restrict__ hWih, const float* __restrict__ hbih) {
    int z = blockIdx.z;
    gemm_body(E, z ? hyp : prem, z ? hWih : pWih, z ? hbih : pbih,
              z ? g_GiH : g_GiP, TBN_, G_, E_);
}

__global__ void __launch_bounds__(256) gemm_yh_k() {
    int z = blockIdx.z;
    gemm_body(z ? g_oH : g_oP, nullptr, z ? g_WhT : g_WyT, nullptr,
              z ? g_hWh : g_Yw, TBN_, N_, N_);
}

__global__ void __launch_bounds__(256) gemm_gihp_k(
        const float* __restrict__ mbih) {
    gemm_body(g_oH, nullptr, g_mWihH, mbih, g_gihp, TBN_, G_, N_);
}

// ------------------------------- persistent GRU ----------------------------
// 128 blocks x 128 threads. Block = 64 b x (8 n x 3 gates = 24 j rows).
// Thread = 4 b x 3 gates via FFMA2 pairs. Weights duplicated (u64) in smem.
// smem: W2 u64[512*24] @0 (98304 B) | Hs f32[2][16][66] @98304 (8448 B) |
//       bsm f32[24] @106752.  Total 106848 B.
__global__ void __launch_bounds__(128, 1) gru_persist_k() {
    u64* W2 = (u64*)g_dynsm;
    float (*Hs)[16][66] = (float (*)[16][66])(g_dynsm + 98304);
    float* bsm = (float*)(g_dynsm + 106752);

    int tid = threadIdx.x;
    int blk = blockIdx.x;
    int nt = blk & 63, bt = blk >> 6;
    int n0 = nt * 8, b0 = bt * 64, j0 = nt * 24;
    int tx = tid & 7, ty = tid >> 3;        // ty 0..15 -> 4 b rows
    int sb = tid >> 1, sk = (tid & 1) * 8;  // stager lanes
    int n = n0 + tx;
    unsigned ep = 0;

    for (int half = 0; half < 2; half++) {
        const float* Gi  = half ? g_GiH : g_GiP;
        const float* Wp  = half ? g_WpH : g_WpP;
        const float* bp  = half ? g_bpH : g_bpP;
        const float* msk = half ? g_maskH : g_maskP;
        float* ob        = half ? g_oH : g_oP;

        __syncthreads();
        for (int i = tid; i < 512 * 24; i += 128) {
            int k = i / 24, j = i - k * 24;
            W2[i] = dup2(Wp[(size_t)(j0 + j) * N_ + k]);
        }
        if (tid < 24) bsm[tid] = bp[j0 + tid];
        __syncthreads();
        float br = bsm[tx * 3 + 0];
        float bz = bsm[tx * 3 + 1];
        float bn = bsm[tx * 3 + 2];

        for (int t = 0; t < T_; t++) {
            int s = half * T_ + t;
            const float* h_prev = (s & 1) ? g_h1 : g_h0;
            float* h_out        = (s & 1) ? g_h0 : g_h1;
            const float* Gi_t = Gi + (size_t)t * B_ * G_;
            float* o_out = ob + (size_t)t * B_ * N_;

            // epilogue operand prefetch (overlaps the GEMM)
            float gr[4], gz[4], gn[4], mv[4], hp[4], op[4];
#pragma unroll
            for (int i = 0; i < 4; i++) {
                int b = b0 + ty * 4 + i;
                gr[i] = Gi_t[(size_t)b * G_ + n];
                gz[i] = Gi_t[(size_t)b * G_ + 512 + n];
                gn[i] = Gi_t[(size_t)b * G_ + 1024 + n];
                mv[i] = msk[t * B_ + b];
                hp[i] = __ldcg(&h_prev[(size_t)b * N_ + n]);
                op[i] = t ? o_out[(ptrdiff_t)((size_t)b * N_ + n) -
                                  (ptrdiff_t)(B_ * N_)]
                          : 0.0f;
            }

            u64 aG0[2] = {0ull, 0ull}, aG1[2] = {0ull, 0ull},
                aG2[2] = {0ull, 0ull};
            const float* src = h_prev + (size_t)(b0 + sb) * N_ + sk;
            float4 p0 = __ldcg((const float4*)src);
            float4 p1 = __ldcg((const float4*)(src + 4));
            for (int cc = 0; cc < 32; cc++) {
                int buf = cc & 1;
                Hs[buf][sk + 0][sb] = p0.x; Hs[buf][sk + 1][sb] = p0.y;
                Hs[buf][sk + 2][sb] = p0.z; Hs[buf][sk + 3][sb] = p0.w;
                Hs[buf][sk + 4][sb] = p1.x; Hs[buf][sk + 5][sb] = p1.y;
                Hs[buf][sk + 6][sb] = p1.z; Hs[buf][sk + 7][sb] = p1.w;
                __syncthreads();
                if (cc + 1 < 32) {
                    const float* s2 =
                        h_prev + (size_t)(b0 + sb) * N_ + (cc + 1) * 16 + sk;
                    p0 = __ldcg((const float4*)s2);
                    p1 = __ldcg((const float4*)(s2 + 4));
                }
                const u64* wbase = &W2[(size_t)cc * 16 * 24];
#pragma unroll
                for (int k = 0; k < 16; k++) {
                    const u64* w = wbase + k * 24 + tx * 3;
                    u64 w0 = w[0], w1 = w[1], w2v = w[2];
                    u64 xA = *(const u64*)&Hs[buf][k][ty * 4];
                    u64 xB = *(const u64*)&Hs[buf][k][ty * 4 + 2];
                    fma2(aG0[0], xA, w0); fma2(aG1[0], xA, w1);
                    fma2(aG2[0], xA, w2v);
                    fma2(aG0[1], xB, w0); fma2(aG1[1], xB, w1);
                    fma2(aG2[1], xB, w2v);
                }
                __syncthreads();
            }
            float2 G0[2] = {up2(aG0[0]), up2(aG0[1])};
            float2 G1[2] = {up2(aG1[0]), up2(aG1[1])};
            float2 G2[2] = {up2(aG2[0]), up2(aG2[1])};
#pragma unroll
            for (int i = 0; i < 4; i++) {
                int p = i >> 1, hh = i & 1;
                float a0 = hh ? G0[p].y : G0[p].x;
                float a1 = hh ? G1[p].y : G1[p].x;
                float a2 = hh ? G2[p].y : G2[p].x;
                int b = b0 + ty * 4 + i;
                float rg = sigm_f(gr[i] + a0 + br);
                float zg = sigm_f(gz[i] + a1 + bz);
                float nv = tanh_f(gn[i] + rg * (a2 + bn));
                float hr = (1.0f - zg) * nv + zg * hp[i];
                h_out[(size_t)b * N_ + n] = hr * mv[i] + hp[i] * (1.0f - mv[i]);
                o_out[(size_t)b * N_ + n] =
                    (t == 0) ? hr : (hr * mv[i] + op[i] * (1.0f - mv[i]));
            }
            ep++;
            grid_bar(g_flagsA, ep);
        }
    }
}

// ------------------------------- persistent attention ----------------------
// 128 blocks x 128 threads.
// smem (bytes): WC u64[1024*24] @0 (196608) | Xs f32[2][16][66] @196608
// (8448) | WrA f32[512*8] @205056 (16384) | s_sh @221440 | wa_sh @223488 |
// wgt @225536 | bsm @226048.  Total 226144.
__global__ void __launch_bounds__(128, 1)
attn_persist_k(const float* __restrict__ Walpha) {
    u64* WC = (u64*)g_dynsm;
    float (*Xs)[16][66] = (float (*)[16][66])(g_dynsm + 196608);
    float* WrA   = (float*)(g_dynsm + 205056);
    float* s_sh  = (float*)(g_dynsm + 221440);
    float* wa_sh = (float*)(g_dynsm + 223488);
    float* wgt   = (float*)(g_dynsm + 225536);
    float* bsm   = (float*)(g_dynsm + 226048);

    int tid = threadIdx.x;
    int blk = blockIdx.x;
    int nt = blk & 63, bt = blk >> 6;
    int n0 = nt * 8, b0 = bt * 64, j0 = nt * 24;
    int tx = tid & 7, ty = tid >> 3;
    int sb = tid >> 1, sk = (tid & 1) * 8;
    int n = n0 + tx;
    int myb = blk;

    // one-time staging
    for (int i = tid; i < 1024 * 24; i += 128) {
        int k = i / 24, j = i - k * 24;
        float w = (k < 512) ? g_AihP[(size_t)(j0 + j) * N_ + k]
                            : g_WpM [(size_t)(j0 + j) * N_ + (k - 512)];
        WC[i] = dup2(w);
    }
    for (int i = tid; i < 512 * 8; i += 128) {
        int k = i >> 3, nl = i & 7;
        WrA[i] = g_WrT[(size_t)(n0 + nl) * N_ + k];
    }
    for (int i = tid; i < N_; i += 128) wa_sh[i] = Walpha[i];
    if (tid < 24) bsm[tid] = g_bpM[j0 + tid];
    __syncthreads();
    float br = bsm[tx * 3 + 0];
    float bz = bsm[tx * 3 + 1];
    float bn = bsm[tx * 3 + 2];

    unsigned ep = 0;
    for (int t = 0; t < T_; t++) {
        const float* r_prev = (t & 1) ? g_r1 : g_r0;
        float* r_out        = (t & 1) ? g_r0 : g_r1;

        // ================= phase A: s = r @ Wr + hWh[t] ====================
        {
            float hw[4];
#pragma unroll
            for (int i = 0; i < 4; i++)
                hw[i] = g_hWh[((size_t)t * B_ + b0 + ty * 4 + i) * N_ + n];
            u64 acc0 = 0ull, acc1 = 0ull;
            const float* src = r_prev + (size_t)(b0 + sb) * N_ + sk;
            float4 p0 = __ldcg((const float4*)src);
            float4 p1 = __ldcg((const float4*)(src + 4));
            for (int cc = 0; cc < 32; cc++) {
                int buf = cc & 1;
                Xs[buf][sk + 0][sb] = p0.x; Xs[buf][sk + 1][sb] = p0.y;
                Xs[buf][sk + 2][sb] = p0.z; Xs[buf][sk + 3][sb] = p0.w;
                Xs[buf][sk + 4][sb] = p1.x; Xs[buf][sk + 5][sb] = p1.y;
                Xs[buf][sk + 6][sb] = p1.z; Xs[buf][sk + 7][sb] = p1.w;
                __syncthreads();
                if (cc + 1 < 32) {
                    const float* s2 =
                        r_prev + (size_t)(b0 + sb) * N_ + (cc + 1) * 16 + sk;
                    p0 = __ldcg((const float4*)s2);
                    p1 = __ldcg((const float4*)(s2 + 4));
                }
                int kb = cc * 16;
#pragma unroll
                for (int k = 0; k < 16; k++) {
                    u64 wd = dup2(WrA[(kb + k) * 8 + tx]);
                    u64 xA = *(const u64*)&Xs[buf][k][ty * 4];
                    u64 xB = *(const u64*)&Xs[buf][k][ty * 4 + 2];
                    fma2(acc0, xA, wd);
                    fma2(acc1, xB, wd);
                }
                __syncthreads();
            }
            float2 vA = up2(acc0), vB = up2(acc1);
            g_s[(size_t)(b0 + ty * 4 + 0) * N_ + n] = vA.x + hw[0];
            g_s[(size_t)(b0 + ty * 4 + 1) * N_ + n] = vA.y + hw[1];
            g_s[(size_t)(b0 + ty * 4 + 2) * N_ + n] = vB.x + hw[2];
            g_s[(size_t)(b0 + ty * 4 + 3) * N_ + n] = vB.y + hw[3];
        }
        ep++; grid_bar(g_flagsB, ep);

        // ============ phase B: alpha + softmax + context (block = b) =======
        {
            for (int i = tid; i < N_; i += 128)
                s_sh[i] = __ldcg(&g_s[(size_t)myb * N_ + i]);
            __syncthreads();
            int warp = tid >> 5, lane = tid & 31;
            for (int tp = warp; tp < T_; tp += 4) {
                const float4* yw =
                    (const float4*)(g_Yw + ((size_t)tp * B_ + myb) * N_);
                const float4* sv4 = (const float4*)s_sh;
                const float4* wa4 = (const float4*)wa_sh;
                float acc = 0.0f;
#pragma unroll
                for (int i = 0; i < 4; i++) {
                    int idx = lane + i * 32;
                    float4 y = yw[idx];
                    float4 sv = sv4[idx];
                    float4 av = wa4[idx];
                    acc += tanh_fast(y.x + sv.x) * av.x;
                    acc += tanh_fast(y.y + sv.y) * av.y;
                    acc += tanh_fast(y.z + sv.z) * av.z;
                    acc += tanh_fast(y.w + sv.w) * av.w;
                }
#pragma unroll
                for (int o = 16; o; o >>= 1)
                    acc += __shfl_xor_sync(0xffffffffu, acc, o);
                if (lane == 0)
                    wgt[tp] = acc - 1000.0f * (1.0f - g_maskP[tp * B_ + myb]);
            }
            __syncthreads();
            if (tid < 32) {
                float mx = -1e30f;
                for (int tt = tid; tt < T_; tt += 32) mx = fmaxf(mx, wgt[tt]);
#pragma unroll
                for (int o = 16; o; o >>= 1)
                    mx = fmaxf(mx, __shfl_xor_sync(0xffffffffu, mx, o));
                float sm = 0.0f;
                for (int tt = tid; tt < T_; tt += 32) {
                    float e = __expf(wgt[tt] - mx);
                    wgt[tt] = e;
                    sm += e;
                }
#pragma unroll
                for (int o = 16; o; o >>= 1)
                    sm += __shfl_xor_sync(0xffffffffu, sm, o);
                float inv = 1.0f / sm;
                for (int tt = tid; tt < T_; tt += 32) wgt[tt] *= inv;
            }
            __syncthreads();
            for (int nn2 = tid; nn2 < N_; nn2 += 128) {
                float acc = 0.0f;
#pragma unroll 4
                for (int tt = 0; tt < T_; tt++)
                    acc += wgt[tt] * g_oP[((size_t)tt * B_ + myb) * N_ + nn2];
                g_a[(size_t)myb * N_ + nn2] = acc;
            }
        }
        ep++; grid_bar(g_flagsB, ep);

        // ====== phase C: match-GRU, K=1024 concat GEMM [a;r]x[Aih|Whh] =====
        {
            const float* gihp_t = g_gihp + (size_t)t * B_ * G_;
            float gr[4], gz[4], gn[4], mv[4], rp[4];
#pragma unroll
            for (int i = 0; i < 4; i++) {
                int b = b0 + ty * 4 + i;
                gr[i] = gihp_t[(size_t)b * G_ + n];
                gz[i] = gihp_t[(size_t)b * G_ + 512 + n];
                gn[i] = gihp_t[(size_t)b * G_ + 1024 + n];
                mv[i] = g_maskH[t * B_ + b];
                rp[i] = __ldcg(&r_prev[(size_t)b * N_ + n]);
            }
            u64 aG0[2] = {0ull, 0ull}, aG1[2] = {0ull, 0ull};
            u64 aNA[2] = {0ull, 0ull}, aNR[2] = {0ull, 0ull};
            const float* src0 = g_a + (size_t)(b0 + sb) * N_ + sk;
            float4 p0 = __ldcg((const float4*)src0);
            float4 p1 = __ldcg((const float4*)(src0 + 4));
            for (int cc = 0; cc < 64; cc++) {
                int buf = cc & 1;
                Xs[buf][sk + 0][sb] = p0.x; Xs[buf][sk + 1][sb] = p0.y;
                Xs[buf][sk + 2][sb] = p0.z; Xs[buf][sk + 3][sb] = p0.w;
                Xs[buf][sk + 4][sb] = p1.x; Xs[buf][sk + 5][sb] = p1.y;
                Xs[buf][sk + 6][sb] = p1.z; Xs[buf][sk + 7][sb] = p1.w;
                __syncthreads();
                if (cc + 1 < 64) {
                    int k0n = (cc + 1) * 16;
                    const float* s2 = (k0n < 512)
                        ? g_a    + (size_t)(b0 + sb) * N_ + k0n + sk
                        : r_prev + (size_t)(b0 + sb) * N_ + (k0n - 512) + sk;
                    p0 = __ldcg((const float4*)s2);
                    p1 = __ldcg((const float4*)(s2 + 4));
                }
                const u64* wbase = &WC[(size_t)cc * 16 * 24];
                if (cc < 32) {
#pragma unroll
                    for (int k = 0; k < 16; k++) {
                        const u64* w = wbase + k * 24 + tx * 3;
                        u64 w0 = w[0], w1 = w[1], w2v = w[2];
                        u64 xA = *(const u64*)&Xs[buf][k][ty * 4];
                        u64 xB = *(const u64*)&Xs[buf][k][ty * 4 + 2];
                        fma2(aG0[0], xA, w0); fma2(aG1[0], xA, w1);
                        fma2(aNA[0], xA, w2v);
                        fma2(aG0[1], xB, w0); fma2(aG1[1], xB, w1);
                        fma2(aNA[1], xB, w2v);
                    }
                } else {
#pragma unroll
                    for (int k = 0; k < 16; k++) {
                        const u64* w = wbase + k * 24 + tx * 3;
                        u64 w0 = w[0], w1 = w[1], w2v = w[2];
                        u64 xA = *(const u64*)&Xs[buf][k][ty * 4];
                        u64 xB = *(const u64*)&Xs[buf][k][ty * 4 + 2];
                        fma2(aG0[0], xA, w0); fma2(aG1[0], xA, w1);
                        fma2(aNR[0], xA, w2v);
                        fma2(aG0[1], xB, w0); fma2(aG1[1], xB, w1);
                        fma2(aNR[1], xB, w2v);
                    }
                }
                __syncthreads();
            }
            float2 G0[2] = {up2(aG0[0]), up2(aG0[1])};
            float2 G1[2] = {up2(aG1[0]), up2(aG1[1])};
            float2 NA[2] = {up2(aNA[0]), up2(aNA[1])};
            float2 NR[2] = {up2(aNR[0]), up2(aNR[1])};
#pragma unroll
            for (int i = 0; i < 4; i++) {
                int p = i >> 1, hh = i & 1;
                float g0v = hh ? G0[p].y : G0[p].x;
                float g1v = hh ? G1[p].y : G1[p].x;
                float nav = hh ? NA[p].y : NA[p].x;
                float nrv = hh ? NR[p].y : NR[p].x;
                int b = b0 + ty * 4 + i;
                float rg = sigm_f(gr[i] + g0v + br);
                float zg = sigm_f(gz[i] + g1v + bz);
                float nv = tanh_f(gn[i] + nav + rg * (nrv + bn));
                float rr = (1.0f - zg) * nv + zg * rp[i];
                r_out[(size_t)b * N_ + n] = rr * mv[i] + rp[i] * (1.0f - mv[i]);
            }
        }
        ep++; grid_bar(g_flagsB, ep);
    }
}

// ------------------------------- logits + log_softmax ----------------------
__global__ void logits_k(const float* __restrict__ W,
                         const float* __restrict__ bo,
                         float* __restrict__ out) {
    int b = blockIdx.x, lane = threadIdx.x;
    float a0 = 0.0f, a1 = 0.0f, a2 = 0.0f;
    for (int k = lane; k < N_; k += 32) {
        float rv = g_r0[(size_t)b * N_ + k];
        a0 += rv * W[k];
        a1 += rv * W[512 + k];
        a2 += rv * W[1024 + k];
    }
#pragma unroll
    for (int o = 16; o; o >>= 1) {
        a0 += __shfl_xor_sync(0xffffffffu, a0, o);
        a1 += __shfl_xor_sync(0xffffffffu, a1, o);
        a2 += __shfl_xor_sync(0xffffffffu, a2, o);
    }
    if (lane == 0) {
        float l0 = a0 + bo[0], l1 = a1 + bo[1], l2 = a2 + bo[2];
        float mx = fmaxf(l0, fmaxf(l1, l2));
        float s = __expf(l0 - mx) + __expf(l1 - mx) + __expf(l2 - mx);
        float lg = mx + logf(s);
        out[b * 3 + 0] = l0 - lg;
        out[b * 3 + 1] = l1 - lg;
        out[b * 3 + 2] = l2 - lg;
    }
}

// ---------------------------------------------------------------------------
extern "C" void kernel_launch(void* const* d_in, const int* in_sizes, int n_in,
                              void* d_out, int out_size) {
    const int*   prem   = (const int*)  d_in[0];
    const int*   hyp    = (const int*)  d_in[1];
    const float* E      = (const float*)d_in[2];
    const float* p_Wih  = (const float*)d_in[3];
    const float* p_Whh  = (const float*)d_in[4];
    const float* p_bih  = (const float*)d_in[5];
    const float* p_bhh  = (const float*)d_in[6];
    const float* h_Wih  = (const float*)d_in[7];
    const float* h_Whh  = (const float*)d_in[8];
    const float* h_bih  = (const float*)d_in[9];
    const float* h_bhh  = (const float*)d_in[10];
    const float* m_Wih  = (const float*)d_in[11];
    const float* m_Whh  = (const float*)d_in[12];
    const float* m_bih  = (const float*)d_in[13];
    const float* m_bhh  = (const float*)d_in[14];
    const float* W_y    = (const float*)d_in[15];
    const float* W_h    = (const float*)d_in[16];
    const float* W_r    = (const float*)d_in[17];
    const float* W_alpha= (const float*)d_in[18];
    const float* out_W  = (const float*)d_in[19];
    const float* out_b  = (const float*)d_in[20];
    float* out = (float*)d_out;

    cudaFuncSetAttribute(gru_persist_k,
                         cudaFuncAttributeMaxDynamicSharedMemorySize, 106880);
    cudaFuncSetAttribute(attn_persist_k,
                         cudaFuncAttributeMaxDynamicSharedMemorySize, 226176);

    // 0: fused prep
    prep_k<<<18752, 256>>>(prem, hyp, W_y, W_h, W_r,
                           p_Whh, p_bhh, h_Whh, h_bhh, m_Whh, m_bhh, m_Wih);
    // 1: input-gate GEMMs (embedding gather fused), both sequences
    gemm_gi_k<<<dim3(G_ / 128, TBN_ / 128, 2), 256>>>(
        prem, hyp, E, p_Wih, p_bih, h_Wih, h_bih);
    // 2: persistent GRU (premise then hypothesis) — ncu-profiled slot
    gru_persist_k<<<128, 128, 106880>>>();
    // 3: Yw and hWh GEMMs
    gemm_yh_k<<<dim3(N_ / 128, TBN_ / 128, 2), 256>>>();
    // 4: gihp GEMM
    gemm_gihp_k<<<dim3(G_ / 128, TBN_ / 128), 256>>>(m_bih);
    // 5: persistent attention + match-GRU loop
    attn_persist_k<<<128, 128, 226176>>>(W_alpha);
    // 6: classifier
    logits_k<<<128, 32>>>(out_W, out_b, out);

    (void)in_sizes; (void)n_in; (void)out_size;
}